// round 1
// baseline (speedup 1.0000x reference)
#include <cuda_runtime.h>
#include <math.h>

#define BATCH 8
#define CIN   64
#define COUT  128
#define EDIM  128
#define HIN   192
#define WIN   384
#define OH    96
#define OW    192
#define TOPK  32
#define OUT6_SIZE (BATCH*COUT*OH*OW)

// ---- scratch (no cudaMalloc allowed) ----
__device__ float d_out2[BATCH*TOPK*OH*OW];   // leaky(conv1*g1), compact channels
__device__ float d_out4[BATCH*TOPK*OH*OW];   // leaky(conv2*g2), compact channels
__device__ int   d_idx1[BATCH*TOPK];
__device__ float d_gv1 [BATCH*TOPK];
__device__ int   d_idx2[BATCH*TOPK];
__device__ float d_gv2 [BATCH*TOPK];
__device__ int   d_slot2[BATCH*COUT];        // channel -> compact slot in d_out4, or -1

__device__ __forceinline__ float leaky(float v) { return v >= 0.f ? v : 0.2f * v; }

// ============================================================================
// Gate kernel: logits = emb @ W + b ; top-32 (tie-break lower index) ; softmax
// over selected ; scatter. grid (BATCH, 2), block 128 (one thread per channel)
// ============================================================================
__global__ void gate_kernel(const float* __restrict__ emb,
                            const float* __restrict__ g1w, const float* __restrict__ g1b,
                            const float* __restrict__ g2w, const float* __restrict__ g2b,
                            float* __restrict__ out) {
    const int b    = blockIdx.x;
    const int gate = blockIdx.y;
    const int c    = threadIdx.x;
    const float* gw = (gate == 0) ? g1w : g2w;
    const float* gb = (gate == 0) ? g1b : g2b;

    __shared__ float s_emb[EDIM];
    __shared__ float s_log[COUT];
    __shared__ float s_exp[COUT];

    s_emb[c] = emb[b * EDIM + c];
    __syncthreads();

    float l = gb[c];
    #pragma unroll 8
    for (int e = 0; e < EDIM; e++) l += s_emb[e] * gw[e * COUT + c];
    s_log[c] = l;
    __syncthreads();

    int rank = 0;
    float m = -1e30f;
    for (int j = 0; j < COUT; j++) {
        float lj = s_log[j];
        if (lj > l || (lj == l && j < c)) rank++;
        if (lj > m) m = lj;
    }
    bool sel = (rank < TOPK);
    float ev = sel ? expf(l - m) : 0.0f;
    s_exp[c] = ev;
    __syncthreads();

    float s = 0.f;
    for (int j = 0; j < COUT; j++) s += s_exp[j];
    float gv = ev / s;

    // write gate output: layout = [out6 | g1 (B*COUT) | g2 (B*COUT)]
    out[OUT6_SIZE + gate * (BATCH * COUT) + b * COUT + c] = gv;

    if (gate == 0) {
        if (sel) { d_idx1[b * TOPK + rank] = c; d_gv1[b * TOPK + rank] = gv; }
    } else {
        d_slot2[b * COUT + c] = sel ? rank : -1;
        if (sel) { d_idx2[b * TOPK + rank] = c; d_gv2[b * TOPK + rank] = gv; }
    }
}

// ============================================================================
// conv1: 3x3 stride 2 pad 1, only the 32 gated output channels.
// grid (72, BATCH): 12 h-tiles x 6 w-tiles of 8x32 output pixels.
// block 256: each thread owns 1 output pixel x 32 channel accumulators.
// Weights gathered to smem, padded to 12 floats/filter for float4 loads.
// ============================================================================
__global__ void __launch_bounds__(256) conv1_kernel(const float* __restrict__ x,
                                                    const float* __restrict__ w1) {
    const int b    = blockIdx.y;
    const int tile = blockIdx.x;
    const int h0 = (tile / 6) * 8;
    const int w0 = (tile % 6) * 32;
    const int tid = threadIdx.x;
    const int py = tid >> 5, px = tid & 31;

    __shared__ int   s_idx[TOPK];
    __shared__ float s_gv[TOPK];
    __shared__ __align__(16) float s_w[16 * TOPK * 12];   // 24.6 KB
    __shared__ float s_x[17 * 65];                        // 4.4 KB

    if (tid < TOPK) { s_idx[tid] = d_idx1[b * TOPK + tid]; s_gv[tid] = d_gv1[b * TOPK + tid]; }

    float acc[TOPK];
    #pragma unroll
    for (int i = 0; i < TOPK; i++) acc[i] = 0.f;

    __syncthreads();

    for (int cc = 0; cc < 4; cc++) {             // 4 chunks of 16 input channels
        // gather weights for this chunk
        for (int i = tid; i < 16 * TOPK * 9; i += 256) {
            int ci_l = i / (TOPK * 9);
            int r = i % (TOPK * 9);
            int co = r / 9, k = r % 9;
            s_w[(ci_l * TOPK + co) * 12 + k] =
                w1[(s_idx[co] * CIN + (cc * 16 + ci_l)) * 9 + k];
        }
        for (int ci_l = 0; ci_l < 16; ci_l++) {
            int ci = cc * 16 + ci_l;
            __syncthreads();
            // stage x patch: rows 2h0-1..2h0+15 (17), cols 2w0-1..2w0+63 (65)
            for (int i = tid; i < 17 * 65; i += 256) {
                int r = i / 65, cl = i % 65;
                int gr = 2 * h0 - 1 + r, gc = 2 * w0 - 1 + cl;
                float v = 0.f;
                if (gr >= 0 && gr < HIN && gc >= 0 && gc < WIN)
                    v = x[((b * CIN + ci) * HIN + gr) * WIN + gc];
                s_x[i] = v;
            }
            __syncthreads();
            const int r0 = 2 * py, c0 = 2 * px;
            float p0 = s_x[r0 * 65 + c0],       p1 = s_x[r0 * 65 + c0 + 1],       p2 = s_x[r0 * 65 + c0 + 2];
            float p3 = s_x[(r0 + 1) * 65 + c0], p4 = s_x[(r0 + 1) * 65 + c0 + 1], p5 = s_x[(r0 + 1) * 65 + c0 + 2];
            float p6 = s_x[(r0 + 2) * 65 + c0], p7 = s_x[(r0 + 2) * 65 + c0 + 1], p8 = s_x[(r0 + 2) * 65 + c0 + 2];
            const float* wb = &s_w[ci_l * TOPK * 12];
            #pragma unroll
            for (int co = 0; co < TOPK; co++) {
                float4 wa = *(const float4*)(wb + co * 12);
                float4 wc = *(const float4*)(wb + co * 12 + 4);
                float  w8 = wb[co * 12 + 8];
                acc[co] += p0 * wa.x + p1 * wa.y + p2 * wa.z + p3 * wa.w
                         + p4 * wc.x + p5 * wc.y + p6 * wc.z + p7 * wc.w + p8 * w8;
            }
        }
        __syncthreads();   // protect s_w before next chunk's gather
    }

    const int h = h0 + py, w = w0 + px;
    #pragma unroll
    for (int co = 0; co < TOPK; co++) {
        float v = leaky(acc[co] * s_gv[co]);
        d_out2[((b * TOPK + co) * OH + h) * OW + w] = v;
    }
}

// ============================================================================
// conv2: 3x3 stride 1 pad 1, 32 compact input channels -> 32 compact outputs.
// Same tiling as conv1.
// ============================================================================
__global__ void __launch_bounds__(256) conv2_kernel(const float* __restrict__ w2) {
    const int b    = blockIdx.y;
    const int tile = blockIdx.x;
    const int h0 = (tile / 6) * 8;
    const int w0 = (tile % 6) * 32;
    const int tid = threadIdx.x;
    const int py = tid >> 5, px = tid & 31;

    __shared__ int   s_idx1[TOPK];
    __shared__ int   s_idx2[TOPK];
    __shared__ float s_gv[TOPK];
    __shared__ __align__(16) float s_w[16 * TOPK * 12];
    __shared__ float s_x[10 * 34];

    if (tid < TOPK) {
        s_idx1[tid] = d_idx1[b * TOPK + tid];
        s_idx2[tid] = d_idx2[b * TOPK + tid];
        s_gv[tid]   = d_gv2[b * TOPK + tid];
    }

    float acc[TOPK];
    #pragma unroll
    for (int i = 0; i < TOPK; i++) acc[i] = 0.f;

    __syncthreads();

    for (int cc = 0; cc < 2; cc++) {             // 2 chunks of 16 input slots
        for (int i = tid; i < 16 * TOPK * 9; i += 256) {
            int ci_l = i / (TOPK * 9);
            int r = i % (TOPK * 9);
            int co = r / 9, k = r % 9;
            s_w[(ci_l * TOPK + co) * 12 + k] =
                w2[(s_idx2[co] * COUT + s_idx1[cc * 16 + ci_l]) * 9 + k];
        }
        for (int ci_l = 0; ci_l < 16; ci_l++) {
            int ci = cc * 16 + ci_l;             // compact slot in d_out2
            __syncthreads();
            for (int i = tid; i < 10 * 34; i += 256) {
                int r = i / 34, cl = i % 34;
                int gr = h0 - 1 + r, gc = w0 - 1 + cl;
                float v = 0.f;
                if (gr >= 0 && gr < OH && gc >= 0 && gc < OW)
                    v = d_out2[((b * TOPK + ci) * OH + gr) * OW + gc];
                s_x[i] = v;
            }
            __syncthreads();
            float p0 = s_x[py * 34 + px],       p1 = s_x[py * 34 + px + 1],       p2 = s_x[py * 34 + px + 2];
            float p3 = s_x[(py + 1) * 34 + px], p4 = s_x[(py + 1) * 34 + px + 1], p5 = s_x[(py + 1) * 34 + px + 2];
            float p6 = s_x[(py + 2) * 34 + px], p7 = s_x[(py + 2) * 34 + px + 1], p8 = s_x[(py + 2) * 34 + px + 2];
            const float* wb = &s_w[ci_l * TOPK * 12];
            #pragma unroll
            for (int co = 0; co < TOPK; co++) {
                float4 wa = *(const float4*)(wb + co * 12);
                float4 wc = *(const float4*)(wb + co * 12 + 4);
                float  w8 = wb[co * 12 + 8];
                acc[co] += p0 * wa.x + p1 * wa.y + p2 * wa.z + p3 * wa.w
                         + p4 * wc.x + p5 * wc.y + p6 * wc.z + p7 * wc.w + p8 * w8;
            }
        }
        __syncthreads();
    }

    const int h = h0 + py, w = w0 + px;
    #pragma unroll
    for (int co = 0; co < TOPK; co++) {
        float v = leaky(acc[co] * s_gv[co]);
        d_out4[((b * TOPK + co) * OH + h) * OW + w] = v;
    }
}

// ============================================================================
// ds: dense 1x1 stride-2 conv + BN(eval) + add sparse out4 + leaky -> out6.
// grid (72, 4, BATCH): 4 groups of 32 output channels.
// ============================================================================
__global__ void __launch_bounds__(256) ds_kernel(const float* __restrict__ x,
                                                 const float* __restrict__ dsw,
                                                 const float* __restrict__ gamma,
                                                 const float* __restrict__ beta,
                                                 float* __restrict__ out) {
    const int b    = blockIdx.z;
    const int cg   = blockIdx.y;                  // channel group (32 each)
    const int tile = blockIdx.x;
    const int h0 = (tile / 6) * 8;
    const int w0 = (tile % 6) * 32;
    const int tid = threadIdx.x;
    const int py = tid >> 5, px = tid & 31;
    const int h = h0 + py, w = w0 + px;

    __shared__ __align__(16) float s_w[CIN][TOPK];   // [ci][co_l] 8 KB
    __shared__ float s_scale[TOPK];
    __shared__ float s_beta[TOPK];
    __shared__ int   s_slot[TOPK];

    for (int i = tid; i < CIN * TOPK; i += 256) {
        int ci = i / TOPK, co_l = i % TOPK;
        s_w[ci][co_l] = dsw[(cg * TOPK + co_l) * CIN + ci];
    }
    if (tid < TOPK) {
        int c = cg * TOPK + tid;
        s_scale[tid] = gamma[c] * rsqrtf(1.0f + 1e-5f);
        s_beta[tid]  = beta[c];
        s_slot[tid]  = d_slot2[b * COUT + c];
    }
    __syncthreads();

    float acc[TOPK];
    #pragma unroll
    for (int i = 0; i < TOPK; i++) acc[i] = 0.f;

    const float* xb = x + ((size_t)b * CIN * HIN + 2 * h) * WIN + 2 * w;
    #pragma unroll 4
    for (int ci = 0; ci < CIN; ci++) {
        float xv = xb[(size_t)ci * HIN * WIN];
        const float* wr = &s_w[ci][0];
        #pragma unroll
        for (int co = 0; co < TOPK; co += 4) {
            float4 wv = *(const float4*)(wr + co);
            acc[co]     += xv * wv.x;
            acc[co + 1] += xv * wv.y;
            acc[co + 2] += xv * wv.z;
            acc[co + 3] += xv * wv.w;
        }
    }

    #pragma unroll
    for (int co = 0; co < TOPK; co++) {
        int c = cg * TOPK + co;
        float v = acc[co] * s_scale[co] + s_beta[co];
        int slot = s_slot[co];
        if (slot >= 0)
            v += d_out4[((b * TOPK + slot) * OH + h) * OW + w];
        out[((b * COUT + c) * OH + h) * OW + w] = leaky(v);
    }
}

// ============================================================================
extern "C" void kernel_launch(void* const* d_in, const int* in_sizes, int n_in,
                              void* d_out, int out_size) {
    const float* x     = (const float*)d_in[0];
    const float* emb   = (const float*)d_in[1];
    const float* w1    = (const float*)d_in[2];
    const float* w2    = (const float*)d_in[3];
    const float* dsw   = (const float*)d_in[4];
    const float* gam   = (const float*)d_in[5];
    const float* bet   = (const float*)d_in[6];
    const float* g1w   = (const float*)d_in[7];
    const float* g1b   = (const float*)d_in[8];
    const float* g2w   = (const float*)d_in[9];
    const float* g2b   = (const float*)d_in[10];
    float* out = (float*)d_out;

    gate_kernel<<<dim3(BATCH, 2), 128>>>(emb, g1w, g1b, g2w, g2b, out);
    conv1_kernel<<<dim3(72, BATCH), 256>>>(x, w1);
    conv2_kernel<<<dim3(72, BATCH), 256>>>(w2);
    ds_kernel<<<dim3(72, 4, BATCH), 256>>>(x, dsw, gam, bet, out);
}